// round 8
// baseline (speedup 1.0000x reference)
#include <cuda_runtime.h>

#define DIM 4096
#define NQ 12
#define DEPTH 4

typedef unsigned long long u64;

// CNOT-ring permutation, gather form (verified rounds 1-7): GF(2)-linear.
__host__ __device__ __forceinline__ constexpr int sig(int x) {
    int r = (x ^ (x >> 1)) & 0x3FF;
    r |= (((x >> 10) ^ (x >> 11) ^ x) & 1) << 10;
    r |= (((x >> 11) ^ x) & 1) << 11;
    return r;
}
// Placement P (inter-layer buffer S0), R2-proven: folds 5->0, 7->1, 6->2.
__host__ __device__ __forceinline__ constexpr int PP(int y) {
    return y ^ ((y >> 5) & 1) ^ (((y >> 7) & 1) << 1) ^ (((y >> 6) & 1) << 2);
}
// Placement Q (intra-layer buffer S1), R2-proven.
__host__ __device__ __forceinline__ constexpr int qq(int y) {
    return y ^ (((y >> 8) ^ (y >> 6)) & 1) ^ (((y >> 7) & 1) << 1)
             ^ (((y >> 5) & 1) << 2) ^ (((y >> 6) & 1) << 3);
}
// Layout-B k-bit embedding: k0..k2 -> index bits 9..11, k3 -> bit 8
__host__ __device__ __forceinline__ constexpr int kbB(int k) {
    return ((k & 7) << 9) | (((k >> 3) & 1) << 8);
}

// ---- packed f32x2 helpers (Blackwell-only; ptxas never auto-fuses these) ----
__device__ __forceinline__ u64 pk(float x, float y) {
    u64 r; asm("mov.b64 %0, {%1,%2};" : "=l"(r) : "f"(x), "f"(y)); return r;
}
__device__ __forceinline__ void upk(u64 r, float& x, float& y) {
    asm("mov.b64 {%0,%1}, %2;" : "=f"(x), "=f"(y) : "l"(r));
}
__device__ __forceinline__ u64 fma2(u64 a, u64 b, u64 c) {
    u64 d; asm("fma.rn.f32x2 %0, %1, %2, %3;" : "=l"(d) : "l"(a), "l"(b), "l"(c));
    return d;
}
__device__ __forceinline__ u64 mul2(u64 a, u64 b) {
    u64 d; asm("mul.rn.f32x2 %0, %1, %2;" : "=l"(d) : "l"(a), "l"(b));
    return d;
}

__global__ __launch_bounds__(256, 1)
void qsim_kernel(const float* __restrict__ x, const float* __restrict__ theta,
                 const float* __restrict__ w, const float* __restrict__ b,
                 float* __restrict__ out) {
    __shared__ float S0[DIM];   // inter-layer buffer (PP placement)
    __shared__ float S1[DIM];   // intra-layer buffer (qq placement)
    __shared__ float CS[DEPTH * NQ];
    __shared__ float SN[DEPTH * NQ];
    __shared__ float red[16];

    const int tid = threadIdx.x;
    const int lane = tid & 31;
    const int wid = tid >> 5;   // 0..7

    // Readout/base index (also used for w prefetch): r = wid<<9 | lane<<4 | k
    const int baseR = (wid << 9) | (lane << 4);

    // -------- prefetch w into registers NOW; consumed ~6us later (hides DRAM) ----
    float4 wv0[4], wv1[4];
    {
        const float4* w0p = reinterpret_cast<const float4*>(w + baseR);
        const float4* w1p = reinterpret_cast<const float4*>(w + DIM + baseR);
#pragma unroll
        for (int j = 0; j < 4; ++j) { wv0[j] = w0p[j]; wv1[j] = w1p[j]; }
    }

    // half-angle cos/sin: angle[d][q] = theta[d][q] + 0.1*x[q]
    if (tid < DEPTH * NQ) {
        const int q = tid % NQ;
        float s, c;
        __sincosf(0.5f * (theta[tid] + 0.1f * x[q]), &s, &c);
        CS[tid] = c;
        SN[tid] = s;
    }
    __syncthreads();

    // Layout A: i = wid<<9 | lane<<4 | k   (k bits 0-3, lane bits 4-8, wid 9-11)
    // Layout B: i = kbB(k) | lane<<3 | wid (wid bits 0-2, lane bits 3-7, k bits 8-11)
    const int baseA = baseR;
    const int baseB = (lane << 3) | wid;
    const int ldA = PP(sig(baseA));   // ^ PP(sig(k))      [A gather, prev ring fused]
    const int stA = qq(baseA);        // ^ k               [A scatter]
    const int ldB = qq(baseB);        // ^ qq(kbB(k))      [B gather]
    const int stB = PP(baseB);        // ^ kbB(k)          [B scatter]

    // ================= Layer 0: product state (all 12 RYs on e0) ============
    {
        float P = 1.f;
#pragma unroll
        for (int bp = 0; bp < 8; ++bp)
            P *= ((baseB >> bp) & 1) ? SN[11 - bp] : CS[11 - bp];
        float t01[4], t23[4];
#pragma unroll
        for (int t = 0; t < 4; ++t) {
            t01[t] = ((t & 1) ? SN[2] : CS[2]) * ((t & 2) ? SN[1] : CS[1]);
            t23[t] = ((t & 1) ? SN[0] : CS[0]) * ((t & 2) ? SN[3] : CS[3]);
        }
#pragma unroll
        for (int k = 0; k < 16; ++k)
            S0[stB ^ kbB(k)] = P * t01[k & 3] * t23[k >> 2];
    }
    __syncthreads();

    // ================= Layers 1..3 ================
#pragma unroll
    for (int d = 1; d < DEPTH; ++d) {
        const float* C = CS + d * NQ;
        const float* Sn = SN + d * NQ;

        // ---- Pass A: gather from S0 (prev ring fused), rotate qubits 11..8
        //      (k bits; packed after scalar k0 step) + qubits 7..3 (lane shfl,
        //      packed), scatter to S1
        u64 va[8];
        {
            const float c = C[11], s = Sn[11];
#pragma unroll
            for (int j = 0; j < 8; ++j) {
                const float x0 = S0[ldA ^ PP(sig(2 * j))];
                const float x1 = S0[ldA ^ PP(sig(2 * j + 1))];
                va[j] = pk(c * x0 - s * x1, s * x0 + c * x1);   // qubit 11 (bit0)
            }
        }
#pragma unroll
        for (int rb = 1; rb < 4; ++rb) {          // k bit rb -> qubit 11-rb
            const int mp = 1 << (rb - 1);         // pack-index stride
            const float c = C[11 - rb], s = Sn[11 - rb];
            const u64 c2 = pk(c, c), s2 = pk(s, s), ns2 = pk(-s, -s);
#pragma unroll
            for (int j = 0; j < 8; ++j)
                if (!(j & mp)) {
                    const u64 lo = va[j], hi = va[j | mp];
                    va[j]      = fma2(c2, lo, mul2(ns2, hi));
                    va[j | mp] = fma2(c2, hi, mul2(s2, lo));
                }
        }
#pragma unroll
        for (int bs = 0; bs < 5; ++bs) {          // lane bit bs -> qubit 7-bs
            const int m = 1 << bs;
            const float c = C[7 - bs], s = Sn[7 - bs];
            const float se = (lane & m) ? s : -s;
            const u64 c2 = pk(c, c), se2 = pk(se, se);
#pragma unroll
            for (int j = 0; j < 8; ++j) {
                const u64 o = __shfl_xor_sync(0xffffffffu, va[j], m);
                va[j] = fma2(c2, va[j], mul2(se2, o));
            }
        }
#pragma unroll
        for (int j = 0; j < 8; ++j) {
            float a0, a1; upk(va[j], a0, a1);
            S1[stA ^ (2 * j)] = a0;
            S1[stA ^ (2 * j + 1)] = a1;
        }
        __syncthreads();

        // ---- Pass B: gather from S1 (pack over k3 = bit8, not rotated here),
        //      rotate qubits 2,1,0 fully packed, scatter to S0
        u64 vb[8];
#pragma unroll
        for (int j = 0; j < 8; ++j)
            vb[j] = pk(S1[ldB ^ qq(kbB(j))], S1[ldB ^ qq(kbB(j | 8))]);

#pragma unroll
        for (int rb = 0; rb < 3; ++rb) {          // k bit rb -> bit 9+rb -> qubit 2-rb
            const int m = 1 << rb;
            const float c = C[2 - rb], s = Sn[2 - rb];
            const u64 c2 = pk(c, c), s2 = pk(s, s), ns2 = pk(-s, -s);
#pragma unroll
            for (int j = 0; j < 8; ++j)
                if (!(j & m)) {
                    const u64 lo = vb[j], hi = vb[j | m];
                    vb[j]     = fma2(c2, lo, mul2(ns2, hi));
                    vb[j | m] = fma2(c2, hi, mul2(s2, lo));
                }
        }
#pragma unroll
        for (int j = 0; j < 8; ++j) {
            float a0, a1; upk(vb[j], a0, a1);
            S0[stB ^ kbB(j)] = a0;
            S0[stB ^ kbB(j | 8)] = a1;
        }
        __syncthreads();
    }

    // ================= Readout (final CNOT ring fused into gather) ================
    // r = wid<<9 | lane<<4 | k; PP(sig(.)) verified conflict-free for this pattern.
    const int rb0 = PP(sig(baseR));
    u64 acc0 = pk(0.f, 0.f), acc1 = pk(0.f, 0.f);
#pragma unroll
    for (int j = 0; j < 8; ++j) {
        const float vx = S0[rb0 ^ PP(sig(2 * j))];
        const float vy = S0[rb0 ^ PP(sig(2 * j + 1))];
        // state store: 8B-aligned pairs (addr = 2 + baseR + 2j, baseR,2j even)
        *reinterpret_cast<float2*>(out + 2 + baseR + 2 * j) = make_float2(vx, vy);
        const u64 v2 = pk(vx, vy);
        const u64 p2 = mul2(v2, v2);
        const float* w0f = reinterpret_cast<const float*>(&wv0[j >> 1]);
        const float* w1f = reinterpret_cast<const float*>(&wv1[j >> 1]);
        const u64 w0p = pk(w0f[(j & 1) * 2], w0f[(j & 1) * 2 + 1]);
        const u64 w1p = pk(w1f[(j & 1) * 2], w1f[(j & 1) * 2 + 1]);
        acc0 = fma2(p2, w0p, acc0);
        acc1 = fma2(p2, w1p, acc1);
    }
    float a0x, a0y, a1x, a1y;
    upk(acc0, a0x, a0y);
    upk(acc1, a1x, a1y);
    float a0 = a0x + a0y, a1 = a1x + a1y;
#pragma unroll
    for (int o = 16; o > 0; o >>= 1) {
        a0 += __shfl_down_sync(0xffffffffu, a0, o);
        a1 += __shfl_down_sync(0xffffffffu, a1, o);
    }
    if (lane == 0) { red[wid] = a0; red[8 + wid] = a1; }
    __syncthreads();
    if (wid == 0 && lane < 16) {
        float rr = (lane < 8) ? red[lane] : red[8 + (lane & 7)];
#pragma unroll
        for (int o = 4; o > 0; o >>= 1)
            rr += __shfl_down_sync(0x0000ffffu, rr, o);
        if (lane == 0) out[0] = rr + b[0];
        if (lane == 8) out[1] = rr + b[1];
    }
}

extern "C" void kernel_launch(void* const* d_in, const int* in_sizes, int n_in,
                              void* d_out, int out_size) {
    const float* x = nullptr;
    const float* th = nullptr;
    const float* w = nullptr;
    const float* b = nullptr;
    for (int i = 0; i < n_in; ++i) {
        const int s = in_sizes[i];
        if (s == NQ) x = (const float*)d_in[i];
        else if (s == DEPTH * NQ) th = (const float*)d_in[i];
        else if (s == 2 * DIM) w = (const float*)d_in[i];
        else if (s == 2) b = (const float*)d_in[i];
    }
    qsim_kernel<<<1, 256>>>(x, th, w, b, (float*)d_out);
}